// round 16
// baseline (speedup 1.0000x reference)
#include <cuda_runtime.h>
#include <cuda_bf16.h>
#include <cstdint>

#define B_ 32
#define L_ 1024
#define D_ 64

typedef __nv_bfloat16 bf16;

// energy bf16 hi/lo splits, [b][j][e] (e contiguous, 128B rows)
__device__ __align__(16) bf16 g_egy_hi[B_ * L_ * D_];
__device__ __align__(16) bf16 g_egy_lo[B_ * L_ * D_];
// energy fp32, [b][e][j] (j contiguous) for the SIMT path
__device__ __align__(16) float g_energyT[B_ * D_ * L_];

// ---------------------------------------------------------------------------
// helpers
// ---------------------------------------------------------------------------
__device__ __forceinline__ uint32_t smem_u32(const void* p) {
    uint32_t a;
    asm("{ .reg .u64 t; cvta.to.shared.u64 t, %1; cvt.u32.u64 %0, t; }"
        : "=r"(a) : "l"(p));
    return a;
}
__device__ __forceinline__ void cp16(void* dst_smem, const void* src) {
    uint32_t s = smem_u32(dst_smem);
    asm volatile("cp.async.cg.shared.global [%0], [%1], 16;" :: "r"(s), "l"(src));
}
__device__ __forceinline__ void cp_commit() { asm volatile("cp.async.commit_group;"); }
template <int N>
__device__ __forceinline__ void cp_wait() {
    asm volatile("cp.async.wait_group %0;" :: "n"(N));
}
__device__ __forceinline__ void ldsm_x4(uint32_t addr, uint32_t r[4]) {
    asm volatile("ldmatrix.sync.aligned.m8n8.x4.shared.b16 {%0,%1,%2,%3}, [%4];"
                 : "=r"(r[0]), "=r"(r[1]), "=r"(r[2]), "=r"(r[3]) : "r"(addr));
}
__device__ __forceinline__ void mma16816(float c[4], const uint32_t a[4],
                                         const uint32_t b0, const uint32_t b1) {
    asm volatile(
        "mma.sync.aligned.m16n8k16.row.col.f32.bf16.bf16.f32 "
        "{%0,%1,%2,%3}, {%4,%5,%6,%7}, {%8,%9}, {%0,%1,%2,%3};"
        : "+f"(c[0]), "+f"(c[1]), "+f"(c[2]), "+f"(c[3])
        : "r"(a[0]), "r"(a[1]), "r"(a[2]), "r"(a[3]), "r"(b0), "r"(b1));
}
__device__ __forceinline__ void ffma2(float2& d, const float2 a, const float2 b) {
    asm("fma.rn.f32x2 %0, %1, %2, %0;"
        : "+l"(reinterpret_cast<unsigned long long&>(d))
        : "l"(reinterpret_cast<const unsigned long long&>(a)),
          "l"(reinterpret_cast<const unsigned long long&>(b)));
}
__device__ __forceinline__ uint32_t swz(uint32_t o) { return o ^ ((o >> 3) & 0x70); }

__device__ __forceinline__ void split2(float a, float b, uint32_t& h, uint32_t& l) {
    bf16 ha = __float2bfloat16_rn(a), hb = __float2bfloat16_rn(b);
    bf16 la = __float2bfloat16_rn(a - __bfloat162float(ha));
    bf16 lb = __float2bfloat16_rn(b - __bfloat162float(hb));
    __nv_bfloat162 hh = __halves2bfloat162(ha, hb);
    __nv_bfloat162 ll = __halves2bfloat162(la, lb);
    h = *reinterpret_cast<uint32_t*>(&hh);
    l = *reinterpret_cast<uint32_t*>(&ll);
}

// ---------------------------------------------------------------------------
// Kernel 1: energy -> bf16 hi/lo [b][j][e].  (EXACT R12/R13 version, proven.)
// grid (8 jb, 32 b), 256 threads
// ---------------------------------------------------------------------------
__global__ __launch_bounds__(256) void energy_kernel(
    const float* __restrict__ enc, const float* __restrict__ W,
    const float* __restrict__ bias) {
    __shared__ float Wt[D_][D_];     // [d][e]
    __shared__ float encs[D_][128];  // [d][j]; reused as enT[e][j]
    const int b = blockIdx.y, jb = blockIdx.x;
    const int tid = threadIdx.x;

    const float4* W4 = reinterpret_cast<const float4*>(W);
#pragma unroll
    for (int i = 0; i < 4; i++) {
        int f = tid + i * 256;
        int e = f >> 4, dq = f & 15;
        float4 w = W4[f];
        Wt[dq * 4 + 0][e] = w.x; Wt[dq * 4 + 1][e] = w.y;
        Wt[dq * 4 + 2][e] = w.z; Wt[dq * 4 + 3][e] = w.w;
    }
    const float4* enc4 =
        reinterpret_cast<const float4*>(enc + ((size_t)b * L_ + (size_t)jb * 128) * D_);
#pragma unroll
    for (int i = 0; i < 8; i++) {
        int f = tid + i * 256;
        int j = f >> 4, dq = f & 15;
        float4 v = enc4[f];
        encs[dq * 4 + 0][j] = v.x; encs[dq * 4 + 1][j] = v.y;
        encs[dq * 4 + 2][j] = v.z; encs[dq * 4 + 3][j] = v.w;
    }
    __syncthreads();

    const int w = tid >> 5, lane = tid & 31;
    const int e0 = w * 8;
    float acc[8][4];
#pragma unroll
    for (int e = 0; e < 8; e++)
#pragma unroll
        for (int q = 0; q < 4; q++) acc[e][q] = 0.f;
#pragma unroll 4
    for (int d = 0; d < D_; d++) {
        float4 ev = *reinterpret_cast<const float4*>(&encs[d][lane * 4]);
        float4 wa = *reinterpret_cast<const float4*>(&Wt[d][e0]);
        float4 wb = *reinterpret_cast<const float4*>(&Wt[d][e0 + 4]);
        float wv[8] = {wa.x, wa.y, wa.z, wa.w, wb.x, wb.y, wb.z, wb.w};
#pragma unroll
        for (int e = 0; e < 8; e++) {
            acc[e][0] = fmaf(wv[e], ev.x, acc[e][0]);
            acc[e][1] = fmaf(wv[e], ev.y, acc[e][1]);
            acc[e][2] = fmaf(wv[e], ev.z, acc[e][2]);
            acc[e][3] = fmaf(wv[e], ev.w, acc[e][3]);
        }
    }
    __syncthreads();
#pragma unroll
    for (int e = 0; e < 8; e++) {
        float bb = bias[e0 + e];
        float4 o = make_float4(acc[e][0] + bb, acc[e][1] + bb,
                               acc[e][2] + bb, acc[e][3] + bb);
        *reinterpret_cast<float4*>(&encs[e0 + e][lane * 4]) = o;  // enT[e][j]
    }
    __syncthreads();

    // emit bf16 hi/lo, layout [j][e]
    const int j = tid >> 1, eh = (tid & 1) * 32;
    const size_t row = (size_t)b * L_ + jb * 128 + j;
    uint32_t hp[16], lp[16];
#pragma unroll
    for (int k = 0; k < 16; k++) {
        float v0 = encs[eh + 2 * k][j];
        float v1 = encs[eh + 2 * k + 1][j];
        split2(v0, v1, hp[k], lp[k]);
    }
    uint4* dh = reinterpret_cast<uint4*>(g_egy_hi + row * D_ + eh);
    uint4* dl = reinterpret_cast<uint4*>(g_egy_lo + row * D_ + eh);
#pragma unroll
    for (int q = 0; q < 4; q++) {
        dh[q] = make_uint4(hp[4 * q], hp[4 * q + 1], hp[4 * q + 2], hp[4 * q + 3]);
        dl[q] = make_uint4(lp[4 * q], lp[4 * q + 1], lp[4 * q + 2], lp[4 * q + 3]);
    }
}

// ---------------------------------------------------------------------------
// Kernel 1b: transpose hi+lo -> fp32 energyT [b][e][j].
// grid (8 jb, 32 b), 256 threads. Isolated from the proven bf16 path.
// ---------------------------------------------------------------------------
__global__ __launch_bounds__(256) void transpose_kernel() {
    __shared__ float tile[D_][129];
    const int b = blockIdx.y, jb = blockIdx.x;
    const int tid = threadIdx.x;

    // read 128 j-rows x 64 e (hi+lo), reconstruct fp32, scatter to tile[e][j]
    const int j = tid >> 1, ebase = (tid & 1) * 32;
    const size_t row = (size_t)b * L_ + jb * 128 + j;
    const uint4* sh = reinterpret_cast<const uint4*>(g_egy_hi + row * D_ + ebase);
    const uint4* sl = reinterpret_cast<const uint4*>(g_egy_lo + row * D_ + ebase);
#pragma unroll
    for (int u = 0; u < 4; u++) {
        uint4 h4 = sh[u], l4 = sl[u];
        uint32_t hv[4] = {h4.x, h4.y, h4.z, h4.w};
        uint32_t lv[4] = {l4.x, l4.y, l4.z, l4.w};
#pragma unroll
        for (int c = 0; c < 4; c++) {
            float2 fh = __bfloat1622float2(*reinterpret_cast<__nv_bfloat162*>(&hv[c]));
            float2 fl = __bfloat1622float2(*reinterpret_cast<__nv_bfloat162*>(&lv[c]));
            const int e = ebase + u * 8 + c * 2;
            tile[e][j] = fh.x + fl.x;
            tile[e + 1][j] = fh.y + fl.y;
        }
    }
    __syncthreads();

    // write out [e][j]: thread -> e = tid>>2, j chunk (tid&3)*32
    const int e = tid >> 2, j0 = (tid & 3) * 32;
    float* dst = g_energyT + (((size_t)b * D_ + e) << 10) + jb * 128 + j0;
#pragma unroll
    for (int i = 0; i < 8; i++) {
        *reinterpret_cast<float4*>(dst + i * 4) =
            make_float4(tile[e][j0 + i * 4], tile[e][j0 + i * 4 + 1],
                        tile[e][j0 + i * 4 + 2], tile[e][j0 + i * 4 + 3]);
    }
}

// ---------------------------------------------------------------------------
// Kernel 2: HYBRID tensor+FMA scores, warp-autonomous, simplified discipline.
// grid (32 tb, 32 b), 512 threads (16 warps). CTA: 32 t x 1024 j.
// warp w: mb = w&1 (m16 block), ng = w>>1, j-band [ng*128,(ng+1)*128).
//   - j [band, band+64): bf16x3 MMA, 4 sub-slabs of 16 j (2-stage B ring,
//     EXACT R12 loader shape, 1 group/sub-slab).
//   - j [band+64, band+128): fp32 FFMA2 SIMT, energyT in 4 phase-chunks of
//     16 k x 64 j (SINGLE 4KB buffer, 1 group/phase, issued a phase ahead).
// Commit order: B0,B1,F0 | per phase p: wait B_p (<2> if p==0 else <3>),
// tensor+exp, wait<0> (F_p), SIMT, refill B_{p+2} & F_{p+1} (empties at tail).
// ---------------------------------------------------------------------------
#define A_HI 0
#define A_LO 4096
#define A32  8192              // fp32 enc [64][40] = 10240 B
#define BRING 18432            // 16 warps x (2 x 4096)
#define FBUF  149504           // 16 warps x 4096
#define SUMS_OFF 215040        // sums[8][32] + sums2[16][32] = 768 floats
#define TOTINV_OFF 218112      // 32 floats
#define SMEM_TOTAL 218240

__global__ __launch_bounds__(512, 1) void scores_hybrid_kernel(
    const float* __restrict__ enc, float* __restrict__ out) {
    extern __shared__ char smem[];
    const uint32_t sb = smem_u32(smem);
    float* sums  = reinterpret_cast<float*>(smem + SUMS_OFF);        // [8][32]
    float* sums2 = sums + 8 * 32;                                    // [16][32]
    float* totinv = reinterpret_cast<float*>(smem + TOTINV_OFF);     // [32]
    float* enc32 = reinterpret_cast<float*>(smem + A32);             // [64][40]

    const int tid = threadIdx.x, w = tid >> 5, lane = tid & 31;
    const int mb = w & 1, ng = w >> 1;
    const int b = blockIdx.y, tb = blockIdx.x, t0 = tb * 32;
    const int g = lane >> 2, qc = lane & 3;          // MMA mapping
    const int tg = lane >> 4, jl = lane & 15;        // SIMT mapping
    const int jband = ng * 128, jb64 = jband + 64;

    // zero sums arrays (sums2 has holes that must be 0)
    {
        if (tid < 768) sums[tid] = 0.f;
        int i1 = tid + 512; if (i1 < 768) sums[i1] = 0.f;
    }

    // ---- A: enc fp32 tile (32 x 64) -> bf16 hi/lo smem + fp32 [k][t] ----
    {
        const float4* src =
            reinterpret_cast<const float4*>(enc + ((size_t)b * L_ + t0) * D_);
        float4 v = src[tid];                 // 512 float4 = whole tile
        int row = tid >> 4, c = tid & 15;    // k = c*4..c*4+3
        uint2 h, l;
        split2(v.x, v.y, h.x, l.x);
        split2(v.z, v.w, h.y, l.y);
        uint32_t off = swz(row * 128 + c * 8);
        *reinterpret_cast<uint2*>(smem + A_HI + off) = h;
        *reinterpret_cast<uint2*>(smem + A_LO + off) = l;
        enc32[(c * 4 + 0) * 40 + row] = v.x;
        enc32[(c * 4 + 1) * 40 + row] = v.y;
        enc32[(c * 4 + 2) * 40 + row] = v.z;
        enc32[(c * 4 + 3) * 40 + row] = v.w;
    }

    // ---- per-warp loaders ----
    const char* bhb = reinterpret_cast<const char*>(g_egy_hi) + (size_t)b * L_ * 128;
    const char* blb = reinterpret_cast<const char*>(g_egy_lo) + (size_t)b * L_ * 128;
    char* const b16base = smem + BRING + w * 8192;
    char* const fbuf = smem + FBUF + w * 4096;

    auto load_b16 = [&](int p2) {        // 16 j-rows hi+lo = 256 chunks, 8/lane
        char* dst = b16base + (p2 & 1) * 4096;
        const size_t j0 = (size_t)(jband + p2 * 16);
#pragma unroll
        for (int i = 0; i < 8; i++) {
            int id = lane + i * 32;
            int split = id >> 7, rem = id & 127, row = rem >> 3, cc = rem & 7;
            cp16(dst + split * 2048 + swz(row * 128 + cc * 16),
                 (split ? blb : bhb) + (j0 + row) * 128 + cc * 16);
        }
        cp_commit();
    };
    auto load_f32 = [&](int q) {         // 16 k x 64 j fp32 = 256 chunks, 8/lane
        const float* src = g_energyT + (((size_t)b * D_ + q * 16) << 10) + jb64;
#pragma unroll
        for (int i = 0; i < 8; i++) {
            int id = lane + i * 32;
            int kk = id >> 4, cc = id & 15;
            cp16(fbuf + kk * 256 + cc * 16,
                 reinterpret_cast<const char*>(src + ((size_t)kk << 10)) + cc * 16);
        }
        cp_commit();
    };

    // prologue: B0(1), B1(2), F0(3)
    load_b16(0); load_b16(1); load_f32(0);

    __syncthreads();   // A tiles visible (only CTA sync before epilogue)

    // ---- A-hi fragments register-resident; A-lo re-ldsm'd per ks ----
    uint32_t af[4][4];
    const uint32_t a_lrow = (uint32_t)(mb * 16 + (lane & 15));
    const uint32_t a_kb = (uint32_t)((lane >> 4) * 8);
#pragma unroll
    for (int ks = 0; ks < 4; ks++)
        ldsm_x4(sb + A_HI + swz(a_lrow * 128 + (a_kb + ks * 16) * 2), af[ks]);

    uint32_t boffs[4];
    {
        const uint32_t b_rowoff = (uint32_t)(((lane >> 4) & 1) * 8 + (lane & 7));
        const uint32_t b_kb = (uint32_t)(((lane >> 3) & 1) * 8);
#pragma unroll
        for (int ks = 0; ks < 4; ks++)
            boffs[ks] = swz(b_rowoff * 128 + (b_kb + ks * 16) * 2);
    }

    float macc[4][2][4];       // tensor acc; exp'd in place per phase
    float2 sacc[8][2];         // SIMT acc [row i][j-pair]; exp'd at end
#pragma unroll
    for (int i = 0; i < 8; i++) {
        sacc[i][0] = make_float2(0.f, 0.f);
        sacc[i][1] = make_float2(0.f, 0.f);
    }

    const int r0 = t0 + mb * 16 + g;     // MMA thread rows
    const int r1 = r0 + 8;
    const int arow = mb * 16 + tg * 8;   // SIMT local row base
    float s0 = 0.f, s1 = 0.f;            // MMA running row sums

#pragma unroll
    for (int p = 0; p < 4; p++) {
        // ===== tensor sub-slab p =====
#pragma unroll
        for (int nt = 0; nt < 2; nt++)
#pragma unroll
            for (int q = 0; q < 4; q++) macc[p][nt][q] = 0.f;

        if (p == 0) { cp_wait<2>(); } else { cp_wait<3>(); }
        __syncwarp();
        {
            const uint32_t bb2 =
                sb + (uint32_t)(BRING + w * 8192 + (p & 1) * 4096);
            float* P0 = macc[p][0];
            float* P1 = macc[p][1];
#pragma unroll
            for (int ks = 0; ks < 4; ks++) {
                uint32_t al[4], bh[4], bl[4];
                ldsm_x4(sb + A_LO + swz(a_lrow * 128 + (a_kb + ks * 16) * 2), al);
                ldsm_x4(bb2 + boffs[ks], bh);
                ldsm_x4(bb2 + 2048 + boffs[ks], bl);
                const uint32_t* ah = af[ks];
                mma16816(P0, ah, bh[0], bh[1]);
                mma16816(P1, ah, bh[2], bh[3]);
                mma16816(P0, al, bh[0], bh[1]);
                mma16816(P1, al, bh[2], bh[3]);
                mma16816(P0, ah, bl[0], bl[1]);
                mma16816(P1, ah, bl[2], bl[3]);
            }
        }
        // tensor epilogue: diag zero + exp + running sums (no max-sub)
#pragma unroll
        for (int nt = 0; nt < 2; nt++) {
            const int j = jband + p * 16 + nt * 8 + qc * 2;
            float* a = macc[p][nt];
            float v0 = (j == r0) ? 0.f : a[0];
            float v1 = (j + 1 == r0) ? 0.f : a[1];
            float v2 = (j == r1) ? 0.f : a[2];
            float v3 = (j + 1 == r1) ? 0.f : a[3];
            v0 = __expf(v0); v1 = __expf(v1); v2 = __expf(v2); v3 = __expf(v3);
            a[0] = v0; a[1] = v1; a[2] = v2; a[3] = v3;
            s0 += v0 + v1; s1 += v2 + v3;
        }

        // ===== SIMT phase p: k in [p*16, p*16+16) =====
        cp_wait<0>();
        __syncwarp();
        {
            const float* fst = reinterpret_cast<const float*>(fbuf);
            const int kb = p * 16;
#pragma unroll
            for (int kl = 0; kl < 16; kl++) {
                const float* ar = enc32 + (kb + kl) * 40 + arow;
                float4 a0 = *reinterpret_cast<const float4*>(ar);
                float4 a1 = *reinterpret_cast<const float4*>(ar + 4);
                float4 bv = *reinterpret_cast<const float4*>(fst + kl * 64 + jl * 4);
                float2 b01 = make_float2(bv.x, bv.y);
                float2 b23 = make_float2(bv.z, bv.w);
                float av[8] = {a0.x, a0.y, a0.z, a0.w, a1.x, a1.y, a1.z, a1.w};
#pragma unroll
                for (int i = 0; i < 8; i++) {
                    float2 aa = make_float2(av[i], av[i]);
                    ffma2(sacc[i][0], aa, b01);
                    ffma2(sacc[i][1], aa, b23);
                }
            }
        }
        __syncwarp();
        // refill: B_{p+2}, F_{p+1} (empties keep group positions fixed)
        if (p + 2 < 4) load_b16(p + 2); else cp_commit();
        if (p + 1 < 4) load_f32(p + 1); else cp_commit();
    }

    // ---- SIMT epilogue: diag zero + exp + row sums over 16 j-lanes ----
    {
        const int j4 = jb64 + jl * 4;
        float rsum[8];
#pragma unroll
        for (int i = 0; i < 8; i++) {
            const int r = t0 + arow + i;
            float v0 = (j4 == r) ? 0.f : sacc[i][0].x;
            float v1 = (j4 + 1 == r) ? 0.f : sacc[i][0].y;
            float v2 = (j4 + 2 == r) ? 0.f : sacc[i][1].x;
            float v3 = (j4 + 3 == r) ? 0.f : sacc[i][1].y;
            v0 = __expf(v0); v1 = __expf(v1); v2 = __expf(v2); v3 = __expf(v3);
            sacc[i][0] = make_float2(v0, v1);
            sacc[i][1] = make_float2(v2, v3);
            rsum[i] = (v0 + v1) + (v2 + v3);
        }
#pragma unroll
        for (int o = 1; o < 16; o <<= 1)
#pragma unroll
            for (int i = 0; i < 8; i++)
                rsum[i] += __shfl_xor_sync(0xffffffffu, rsum[i], o);
        if (jl == 0) {
#pragma unroll
            for (int i = 0; i < 8; i++)
                sums2[w * 32 + arow + i] = rsum[i];
        }
    }

    // ---- MMA row sums ----
#pragma unroll
    for (int o = 1; o < 4; o <<= 1) {
        s0 += __shfl_xor_sync(0xffffffffu, s0, o);
        s1 += __shfl_xor_sync(0xffffffffu, s1, o);
    }
    if (qc == 0) {
        sums[ng * 32 + mb * 16 + g] = s0;
        sums[ng * 32 + mb * 16 + g + 8] = s1;
    }
    __syncthreads();

    // ---- totals ----
    if (tid < 32) {
        float t = 0.f;
#pragma unroll
        for (int q = 0; q < 8; q++) t += sums[q * 32 + tid];
#pragma unroll
        for (int q = 0; q < 16; q++) t += sums2[q * 32 + tid];
        totinv[tid] = 1.0f / t;
    }
    __syncthreads();

    // ---- stores: MMA cols ----
    {
        const float rinv0 = totinv[mb * 16 + g], rinv1 = totinv[mb * 16 + g + 8];
        float* out0 = out + (((size_t)r0 * B_ + b) << 10);
        float* out1 = out + (((size_t)r1 * B_ + b) << 10);
#pragma unroll
        for (int p = 0; p < 4; p++)
#pragma unroll
            for (int nt = 0; nt < 2; nt++) {
                const int j = jband + p * 16 + nt * 8 + qc * 2;
                float* a = macc[p][nt];
                *reinterpret_cast<float2*>(out0 + j) =
                    make_float2(a[0] * rinv0, a[1] * rinv0);
                *reinterpret_cast<float2*>(out1 + j) =
                    make_float2(a[2] * rinv1, a[3] * rinv1);
            }
    }
    // ---- stores: SIMT cols ----
    {
#pragma unroll
        for (int i = 0; i < 8; i++) {
            const int r = t0 + arow + i;
            const float ri = totinv[arow + i];
            float4 o = make_float4(sacc[i][0].x * ri, sacc[i][0].y * ri,
                                   sacc[i][1].x * ri, sacc[i][1].y * ri);
            *reinterpret_cast<float4*>(
                out + (((size_t)r * B_ + b) << 10) + jb64 + jl * 4) = o;
        }
    }
}

// ---------------------------------------------------------------------------
extern "C" void kernel_launch(void* const* d_in, const int* in_sizes, int n_in,
                              void* d_out, int out_size) {
    (void)in_sizes; (void)n_in; (void)out_size;
    const float* enc  = (const float*)d_in[0];
    const float* W    = (const float*)d_in[1];
    const float* bias = (const float*)d_in[2];
    float* out = (float*)d_out;

    static int configured = 0;
    if (!configured) {
        cudaFuncSetAttribute(scores_hybrid_kernel,
                             cudaFuncAttributeMaxDynamicSharedMemorySize, SMEM_TOTAL);
        configured = 1;
    }

    energy_kernel<<<dim3(8, 32), 256>>>(enc, W, bias);
    transpose_kernel<<<dim3(8, 32), 256>>>();
    scores_hybrid_kernel<<<dim3(32, 32), 512, SMEM_TOTAL>>>(enc, out);
}

// round 17
// speedup vs baseline: 1.0409x; 1.0409x over previous
#include <cuda_runtime.h>
#include <cuda_bf16.h>
#include <cstdint>

#define B_ 32
#define L_ 1024
#define D_ 64

typedef __nv_bfloat16 bf16;

// energy bf16 hi/lo splits, [b][j][e] (e contiguous, 128B rows)
__device__ __align__(16) bf16 g_egy_hi[B_ * L_ * D_];
__device__ __align__(16) bf16 g_egy_lo[B_ * L_ * D_];
// energy fp32, [b][e][j] (j contiguous) for the SIMT path
__device__ __align__(16) float g_energyT[B_ * D_ * L_];

// ---------------------------------------------------------------------------
// helpers
// ---------------------------------------------------------------------------
__device__ __forceinline__ uint32_t smem_u32(const void* p) {
    uint32_t a;
    asm("{ .reg .u64 t; cvta.to.shared.u64 t, %1; cvt.u32.u64 %0, t; }"
        : "=r"(a) : "l"(p));
    return a;
}
__device__ __forceinline__ void cp16(void* dst_smem, const void* src) {
    uint32_t s = smem_u32(dst_smem);
    asm volatile("cp.async.cg.shared.global [%0], [%1], 16;" :: "r"(s), "l"(src));
}
__device__ __forceinline__ void cp_commit() { asm volatile("cp.async.commit_group;"); }
template <int N>
__device__ __forceinline__ void cp_wait() {
    asm volatile("cp.async.wait_group %0;" :: "n"(N));
}
__device__ __forceinline__ void ldsm_x4(uint32_t addr, uint32_t r[4]) {
    asm volatile("ldmatrix.sync.aligned.m8n8.x4.shared.b16 {%0,%1,%2,%3}, [%4];"
                 : "=r"(r[0]), "=r"(r[1]), "=r"(r[2]), "=r"(r[3]) : "r"(addr));
}
__device__ __forceinline__ void mma16816(float c[4], const uint32_t a[4],
                                         const uint32_t b0, const uint32_t b1) {
    asm volatile(
        "mma.sync.aligned.m16n8k16.row.col.f32.bf16.bf16.f32 "
        "{%0,%1,%2,%3}, {%4,%5,%6,%7}, {%8,%9}, {%0,%1,%2,%3};"
        : "+f"(c[0]), "+f"(c[1]), "+f"(c[2]), "+f"(c[3])
        : "r"(a[0]), "r"(a[1]), "r"(a[2]), "r"(a[3]), "r"(b0), "r"(b1));
}
__device__ __forceinline__ void ffma2(float2& d, const float2 a, const float2 b) {
    asm("fma.rn.f32x2 %0, %1, %2, %0;"
        : "+l"(reinterpret_cast<unsigned long long&>(d))
        : "l"(reinterpret_cast<const unsigned long long&>(a)),
          "l"(reinterpret_cast<const unsigned long long&>(b)));
}
__device__ __forceinline__ uint32_t swz(uint32_t o) { return o ^ ((o >> 3) & 0x70); }

__device__ __forceinline__ void split2(float a, float b, uint32_t& h, uint32_t& l) {
    bf16 ha = __float2bfloat16_rn(a), hb = __float2bfloat16_rn(b);
    bf16 la = __float2bfloat16_rn(a - __bfloat162float(ha));
    bf16 lb = __float2bfloat16_rn(b - __bfloat162float(hb));
    __nv_bfloat162 hh = __halves2bfloat162(ha, hb);
    __nv_bfloat162 ll = __halves2bfloat162(la, lb);
    h = *reinterpret_cast<uint32_t*>(&hh);
    l = *reinterpret_cast<uint32_t*>(&ll);
}

// ---------------------------------------------------------------------------
// Kernel 1: energy -> bf16 hi/lo [b][j][e]. (proven R12 version)
// grid (8 jb, 32 b), 256 threads
// ---------------------------------------------------------------------------
__global__ __launch_bounds__(256) void energy_kernel(
    const float* __restrict__ enc, const float* __restrict__ W,
    const float* __restrict__ bias) {
    __shared__ float Wt[D_][D_];
    __shared__ float encs[D_][128];
    const int b = blockIdx.y, jb = blockIdx.x;
    const int tid = threadIdx.x;

    const float4* W4 = reinterpret_cast<const float4*>(W);
#pragma unroll
    for (int i = 0; i < 4; i++) {
        int f = tid + i * 256;
        int e = f >> 4, dq = f & 15;
        float4 w = W4[f];
        Wt[dq * 4 + 0][e] = w.x; Wt[dq * 4 + 1][e] = w.y;
        Wt[dq * 4 + 2][e] = w.z; Wt[dq * 4 + 3][e] = w.w;
    }
    const float4* enc4 =
        reinterpret_cast<const float4*>(enc + ((size_t)b * L_ + (size_t)jb * 128) * D_);
#pragma unroll
    for (int i = 0; i < 8; i++) {
        int f = tid + i * 256;
        int j = f >> 4, dq = f & 15;
        float4 v = enc4[f];
        encs[dq * 4 + 0][j] = v.x; encs[dq * 4 + 1][j] = v.y;
        encs[dq * 4 + 2][j] = v.z; encs[dq * 4 + 3][j] = v.w;
    }
    __syncthreads();

    const int w = tid >> 5, lane = tid & 31;
    const int e0 = w * 8;
    float acc[8][4];
#pragma unroll
    for (int e = 0; e < 8; e++)
#pragma unroll
        for (int q = 0; q < 4; q++) acc[e][q] = 0.f;
#pragma unroll 4
    for (int d = 0; d < D_; d++) {
        float4 ev = *reinterpret_cast<const float4*>(&encs[d][lane * 4]);
        float4 wa = *reinterpret_cast<const float4*>(&Wt[d][e0]);
        float4 wb = *reinterpret_cast<const float4*>(&Wt[d][e0 + 4]);
        float wv[8] = {wa.x, wa.y, wa.z, wa.w, wb.x, wb.y, wb.z, wb.w};
#pragma unroll
        for (int e = 0; e < 8; e++) {
            acc[e][0] = fmaf(wv[e], ev.x, acc[e][0]);
            acc[e][1] = fmaf(wv[e], ev.y, acc[e][1]);
            acc[e][2] = fmaf(wv[e], ev.z, acc[e][2]);
            acc[e][3] = fmaf(wv[e], ev.w, acc[e][3]);
        }
    }
    __syncthreads();
#pragma unroll
    for (int e = 0; e < 8; e++) {
        float bb = bias[e0 + e];
        float4 o = make_float4(acc[e][0] + bb, acc[e][1] + bb,
                               acc[e][2] + bb, acc[e][3] + bb);
        *reinterpret_cast<float4*>(&encs[e0 + e][lane * 4]) = o;
    }
    __syncthreads();

    const int j = tid >> 1, eh = (tid & 1) * 32;
    const size_t row = (size_t)b * L_ + jb * 128 + j;
    uint32_t hp[16], lp[16];
#pragma unroll
    for (int k = 0; k < 16; k++) {
        float v0 = encs[eh + 2 * k][j];
        float v1 = encs[eh + 2 * k + 1][j];
        split2(v0, v1, hp[k], lp[k]);
    }
    uint4* dh = reinterpret_cast<uint4*>(g_egy_hi + row * D_ + eh);
    uint4* dl = reinterpret_cast<uint4*>(g_egy_lo + row * D_ + eh);
#pragma unroll
    for (int q = 0; q < 4; q++) {
        dh[q] = make_uint4(hp[4 * q], hp[4 * q + 1], hp[4 * q + 2], hp[4 * q + 3]);
        dl[q] = make_uint4(lp[4 * q], lp[4 * q + 1], lp[4 * q + 2], lp[4 * q + 3]);
    }
}

// ---------------------------------------------------------------------------
// Kernel 1b: transpose hi+lo -> fp32 energyT [b][e][j]. (proven R16 version)
// ---------------------------------------------------------------------------
__global__ __launch_bounds__(256) void transpose_kernel() {
    __shared__ float tile[D_][129];
    const int b = blockIdx.y, jb = blockIdx.x;
    const int tid = threadIdx.x;

    const int j = tid >> 1, ebase = (tid & 1) * 32;
    const size_t row = (size_t)b * L_ + jb * 128 + j;
    const uint4* sh = reinterpret_cast<const uint4*>(g_egy_hi + row * D_ + ebase);
    const uint4* sl = reinterpret_cast<const uint4*>(g_egy_lo + row * D_ + ebase);
#pragma unroll
    for (int u = 0; u < 4; u++) {
        uint4 h4 = sh[u], l4 = sl[u];
        uint32_t hv[4] = {h4.x, h4.y, h4.z, h4.w};
        uint32_t lv[4] = {l4.x, l4.y, l4.z, l4.w};
#pragma unroll
        for (int c = 0; c < 4; c++) {
            float2 fh = __bfloat1622float2(*reinterpret_cast<__nv_bfloat162*>(&hv[c]));
            float2 fl = __bfloat1622float2(*reinterpret_cast<__nv_bfloat162*>(&lv[c]));
            const int e = ebase + u * 8 + c * 2;
            tile[e][j] = fh.x + fl.x;
            tile[e + 1][j] = fh.y + fl.y;
        }
    }
    __syncthreads();

    const int e = tid >> 2, j0 = (tid & 3) * 32;
    float* dst = g_energyT + (((size_t)b * D_ + e) << 10) + jb * 128 + j0;
#pragma unroll
    for (int i = 0; i < 8; i++) {
        *reinterpret_cast<float4*>(dst + i * 4) =
            make_float4(tile[e][j0 + i * 4], tile[e][j0 + i * 4 + 1],
                        tile[e][j0 + i * 4 + 2], tile[e][j0 + i * 4 + 3]);
    }
}

// ---------------------------------------------------------------------------
// Kernel 2: HYBRID v3 — instruction-interleaved tensor+FMA, warp-autonomous.
// grid (32 tb, 32 b), 512 threads (16 warps). CTA: 32 t x 1024 j.
// warp w: mb = w&1 (m16 block), ng = w>>1, j-band [ng*128,(ng+1)*128).
//   - j [band, band+64): bf16x3 MMA, 8 phases of 8 j.
//   - j [band+64, band+128): fp32 FFMA2, 8 phases of 8 k.
// Per phase body interleaves 12 MMAs with 128 ffma2 (one straight-line block)
// so tensor and FMA pipes run CONCURRENTLY. Rings: B 2x2KB, F 2x2KB per warp.
// Groups: 2/phase (B_p, F_p); prologue B0,F0,B1,F1; wait<2> per phase head.
// ---------------------------------------------------------------------------
#define A_HI 0
#define A_LO 4096
#define A32  8192               // fp32 enc [64][40] = 10240 B
#define BRING 18432             // 16 warps x 4096 (2 x 2KB)
#define FRING 83968             // 16 warps x 4096 (2 x 2KB)
#define SUMS_OFF 149504         // 768 floats
#define TOTINV_OFF 152576       // 32 floats
#define SMEM_TOTAL 152704

__global__ __launch_bounds__(512, 1) void scores_hybrid_kernel(
    const float* __restrict__ enc, float* __restrict__ out) {
    extern __shared__ char smem[];
    const uint32_t sb = smem_u32(smem);
    float* sums  = reinterpret_cast<float*>(smem + SUMS_OFF);        // [8][32]
    float* sums2 = sums + 8 * 32;                                    // [16][32]
    float* totinv = reinterpret_cast<float*>(smem + TOTINV_OFF);     // [32]
    float* enc32 = reinterpret_cast<float*>(smem + A32);             // [64][40]

    const int tid = threadIdx.x, w = tid >> 5, lane = tid & 31;
    const int mb = w & 1, ng = w >> 1;
    const int b = blockIdx.y, tb = blockIdx.x, t0 = tb * 32;
    const int g = lane >> 2, qc = lane & 3;          // MMA mapping
    const int tg = lane >> 4, jl = lane & 15;        // SIMT mapping
    const int jband = ng * 128, jb64 = jband + 64;

    // zero sums arrays
    if (tid < 768) sums[tid] = 0.f;
    { int i1 = tid + 512; if (i1 < 768) sums[i1] = 0.f; }

    // ---- A: enc fp32 tile (32 x 64) -> bf16 hi/lo smem + fp32 [k][t] ----
    {
        const float4* src =
            reinterpret_cast<const float4*>(enc + ((size_t)b * L_ + t0) * D_);
        float4 v = src[tid];
        int row = tid >> 4, c = tid & 15;
        uint2 h, l;
        split2(v.x, v.y, h.x, l.x);
        split2(v.z, v.w, h.y, l.y);
        uint32_t off = swz(row * 128 + c * 8);
        *reinterpret_cast<uint2*>(smem + A_HI + off) = h;
        *reinterpret_cast<uint2*>(smem + A_LO + off) = l;
        enc32[(c * 4 + 0) * 40 + row] = v.x;
        enc32[(c * 4 + 1) * 40 + row] = v.y;
        enc32[(c * 4 + 2) * 40 + row] = v.z;
        enc32[(c * 4 + 3) * 40 + row] = v.w;
    }

    // ---- per-warp loaders ----
    const char* bhb = reinterpret_cast<const char*>(g_egy_hi) + (size_t)b * L_ * 128;
    const char* blb = reinterpret_cast<const char*>(g_egy_lo) + (size_t)b * L_ * 128;
    char* const b16base = smem + BRING + w * 4096;
    char* const fbuf = smem + FRING + w * 4096;

    auto load_b16 = [&](int p) {     // 8 j-rows hi+lo = 128 chunks, 4/lane
        char* dst = b16base + (p & 1) * 2048;
        const size_t j0 = (size_t)(jband + p * 8);
#pragma unroll
        for (int i = 0; i < 4; i++) {
            int id = lane + i * 32;
            int split = id >> 6, rem = id & 63, row = rem >> 3, cc = rem & 7;
            cp16(dst + split * 1024 + swz(row * 128 + cc * 16),
                 (split ? blb : bhb) + (j0 + row) * 128 + cc * 16);
        }
        cp_commit();
    };
    auto load_f32 = [&](int p) {     // 8 k x 64 j fp32 = 128 chunks, 4/lane
        char* dst = fbuf + (p & 1) * 2048;
        const float* src = g_energyT + (((size_t)b * D_ + p * 8) << 10) + jb64;
#pragma unroll
        for (int i = 0; i < 4; i++) {
            int id = lane + i * 32;
            int kk = id >> 4, cc = id & 15;
            cp16(dst + kk * 256 + cc * 16,
                 reinterpret_cast<const char*>(src + ((size_t)kk << 10)) + cc * 16);
        }
        cp_commit();
    };

    // prologue groups: B0, F0, B1, F1
    load_b16(0); load_f32(0); load_b16(1); load_f32(1);

    __syncthreads();   // A tiles visible (only CTA sync before epilogue)

    // ---- A-hi fragments resident; A-lo re-ldsm'd per phase ----
    uint32_t af[4][4], aoffs[4];
    const uint32_t a_lrow = (uint32_t)(mb * 16 + (lane & 15));
    const uint32_t a_kb = (uint32_t)((lane >> 4) * 8);
#pragma unroll
    for (int ks = 0; ks < 4; ks++) {
        aoffs[ks] = swz(a_lrow * 128 + (a_kb + ks * 16) * 2);
        ldsm_x4(sb + A_HI + aoffs[ks], af[ks]);
    }
    // B fragment offsets: pair u covers ks=2u,2u+1 (4 matrices)
    uint32_t boffs[2];
#pragma unroll
    for (int u = 0; u < 2; u++)
        boffs[u] = swz((lane & 7) * 128 + (lane >> 3) * 16 + u * 64);

    float macc[8][4];          // tensor acc per phase; exp'd in place
    float2 sacc[8][2];         // SIMT acc [row i][j-pair]; exp'd at end
#pragma unroll
    for (int i = 0; i < 8; i++) {
        sacc[i][0] = make_float2(0.f, 0.f);
        sacc[i][1] = make_float2(0.f, 0.f);
    }

    const int r0 = t0 + mb * 16 + g;
    const int r1 = r0 + 8;
    const int arow = mb * 16 + tg * 8;   // SIMT local row base
    float s0 = 0.f, s1 = 0.f;

    const uint32_t bglob = sb + (uint32_t)(BRING + w * 4096);

#pragma unroll
    for (int p = 0; p < 8; p++) {
        cp_wait<2>();          // B_p, F_p resident; prefetch pair stays in flight
        __syncwarp();

        float* P = macc[p];
        P[0] = 0.f; P[1] = 0.f; P[2] = 0.f; P[3] = 0.f;
        const uint32_t bb2 = bglob + (p & 1) * 2048;
        const float* fst = reinterpret_cast<const float*>(fbuf + (p & 1) * 2048);
        const int kb = p * 8;

        // interleaved body: per u, 6 MMAs + 4 SIMT k-rows (64 ffma2)
#pragma unroll
        for (int u = 0; u < 2; u++) {
            uint32_t bh[4], bl[4], al0[4], al1[4];
            ldsm_x4(bb2 + boffs[u], bh);
            ldsm_x4(bb2 + 1024 + boffs[u], bl);
            ldsm_x4(sb + A_LO + aoffs[2 * u], al0);
            ldsm_x4(sb + A_LO + aoffs[2 * u + 1], al1);
            mma16816(P, af[2 * u],     bh[0], bh[1]);
            mma16816(P, af[2 * u + 1], bh[2], bh[3]);
            mma16816(P, al0,           bh[0], bh[1]);
            mma16816(P, al1,           bh[2], bh[3]);
            mma16816(P, af[2 * u],     bl[0], bl[1]);
            mma16816(P, af[2 * u + 1], bl[2], bl[3]);
#pragma unroll
            for (int kl2 = 0; kl2 < 4; kl2++) {
                const int kl = u * 4 + kl2;
                const float* ar = enc32 + (kb + kl) * 40 + arow;
                float4 a0 = *reinterpret_cast<const float4*>(ar);
                float4 a1 = *reinterpret_cast<const float4*>(ar + 4);
                float4 bv = *reinterpret_cast<const float4*>(fst + kl * 64 + jl * 4);
                float2 b01 = make_float2(bv.x, bv.y);
                float2 b23 = make_float2(bv.z, bv.w);
                float av[8] = {a0.x, a0.y, a0.z, a0.w, a1.x, a1.y, a1.z, a1.w};
#pragma unroll
                for (int i = 0; i < 8; i++) {
                    float2 aa = make_float2(av[i], av[i]);
                    ffma2(sacc[i][0], aa, b01);
                    ffma2(sacc[i][1], aa, b23);
                }
            }
        }
        __syncwarp();
        // refill B_{p+2}, F_{p+2} (empties keep group count uniform)
        if (p + 2 < 8) { load_b16(p + 2); load_f32(p + 2); }
        else { cp_commit(); cp_commit(); }

        // tensor epilogue: diag zero + exp + running sums (no max-sub)
        {
            const int j = jband + p * 8 + qc * 2;
            float v0 = (j == r0) ? 0.f : P[0];
            float v1 = (j + 1 == r0) ? 0.f : P[1];
            float v2 = (j == r1) ? 0.f : P[2];
            float v3 = (j + 1 == r1) ? 0.f : P[3];
            v0 = __expf(v0); v1 = __expf(v1); v2 = __expf(v2); v3 = __expf(v3);
            P[0] = v0; P[1] = v1; P[2] = v2; P[3] = v3;
            s0 += v0 + v1; s1 += v2 + v3;
        }
    }

    // ---- SIMT epilogue: diag zero + exp + row sums over 16 j-lanes ----
    {
        const int j4 = jb64 + jl * 4;
        float rsum[8];
#pragma unroll
        for (int i = 0; i < 8; i++) {
            const int r = t0 + arow + i;
            float v0 = (j4 == r) ? 0.f : sacc[i][0].x;
            float v1 = (j4 + 1 == r) ? 0.f : sacc[i][0].y;
            float v2 = (j4 + 2 == r) ? 0.f : sacc[i][1].x;
            float v3 = (j4 + 3 == r) ? 0.f : sacc[i][1].y;
            v0 = __expf(v0); v1 = __expf(v1); v2 = __expf(v2); v3 = __expf(v3);
            sacc[i][0] = make_float2(v0, v1);
            sacc[i][1] = make_float2(v2, v3);
            rsum[i] = (v0 + v1) + (v2 + v3);
        }
#pragma unroll
        for (int o = 1; o < 16; o <<= 1)
#pragma unroll
            for (int i = 0; i < 8; i++)
                rsum[i] += __shfl_xor_sync(0xffffffffu, rsum[i], o);
        if (jl == 0) {
#pragma unroll
            for (int i = 0; i < 8; i++)
                sums2[w * 32 + arow + i] = rsum[i];
        }
    }

    // ---- MMA row sums ----
#pragma unroll
    for (int o = 1; o < 4; o <<= 1) {
        s0 += __shfl_xor_sync(0xffffffffu, s0, o);
        s1 += __shfl_xor_sync(0xffffffffu, s1, o);
    }
    if (qc == 0) {
        sums[ng * 32 + mb * 16 + g] = s0;
        sums[ng * 32 + mb * 16 + g + 8] = s1;
    }
    __syncthreads();

    // ---- totals ----
    if (tid < 32) {
        float t = 0.f;
#pragma unroll
        for (int q = 0; q < 8; q++) t += sums[q * 32 + tid];
#pragma unroll
        for (int q = 0; q < 16; q++) t += sums2[q * 32 + tid];
        totinv[tid] = 1.0f / t;
    }
    __syncthreads();

    // ---- stores: MMA cols ----
    {
        const float rinv0 = totinv[mb * 16 + g], rinv1 = totinv[mb * 16 + g + 8];
        float* out0 = out + (((size_t)r0 * B_ + b) << 10);
        float* out1 = out + (((size_t)r1 * B_ + b) << 10);
#pragma unroll
        for (int p = 0; p < 8; p++) {
            const int j = jband + p * 8 + qc * 2;
            float* a = macc[p];
            *reinterpret_cast<float2*>(out0 + j) =
                make_float2(a[0] * rinv0, a[1] * rinv0);
            *reinterpret_cast<float2*>(out1 + j) =
                make_float2(a[2] * rinv1, a[3] * rinv1);
        }
    }
    // ---- stores: SIMT cols ----
    {
#pragma unroll
        for (int i = 0; i < 8; i++) {
            const int r = t0 + arow + i;
            const float ri = totinv[arow + i];
            float4 o = make_float4(sacc[i][0].x * ri, sacc[i][0].y * ri,
                                   sacc[i][1].x * ri, sacc[i][1].y * ri);
            *reinterpret_cast<float4*>(
                out + (((size_t)r * B_ + b) << 10) + jb64 + jl * 4) = o;
        }
    }
}

// ---------------------------------------------------------------------------
extern "C" void kernel_launch(void* const* d_in, const int* in_sizes, int n_in,
                              void* d_out, int out_size) {
    (void)in_sizes; (void)n_in; (void)out_size;
    const float* enc  = (const float*)d_in[0];
    const float* W    = (const float*)d_in[1];
    const float* bias = (const float*)d_in[2];
    float* out = (float*)d_out;

    static int configured = 0;
    if (!configured) {
        cudaFuncSetAttribute(scores_hybrid_kernel,
                             cudaFuncAttributeMaxDynamicSharedMemorySize, SMEM_TOTAL);
        configured = 1;
    }

    energy_kernel<<<dim3(8, 32), 256>>>(enc, W, bias);
    transpose_kernel<<<dim3(8, 32), 256>>>();
    scores_hybrid_kernel<<<dim3(32, 32), 512, SMEM_TOTAL>>>(enc, out);
}